// round 5
// baseline (speedup 1.0000x reference)
#include <cuda_runtime.h>

// out[b,t,c] = sum_s exp(-4*(sw[b,t] + s - t)^2) * input[b,s,c]
// WIDTH=0.25 -> weight = exp(-4 d^2). 3-tap window {r-1, r, r+1} around
// r = round(t - sw): dropped taps have |d| >= 1.5 -> wgt <= 1.23e-4 vs kept
// sum >= 0.74 -> worst-case rel err ~3e-4 (threshold 1e-3; measured 4.5e-5).
//
// B=16, S=4096, T=2048, C=128.
// Band-staging design: block owns 32 consecutive t. All taps lie in the
// contiguous row band [t0-12, t0+44) for |sw| <= 10.5 (actual max ~4.4).
// Stage the 56-row band (28.7 KB) into SMEM with 7 coalesced independent
// LDG.128/thread (high MLP, no persistent regs), then compute from SMEM
// (LDS ~29cyc instead of ~300cyc L2 gather). Rows with s<0 are zero-filled,
// which makes their taps contribute exactly 0 (matches reference). A
// predicated global-load fallback covers the (never-taken) out-of-band case.

#define S_DIM 4096
#define T_DIM 2048
#define C_DIM 128
#define C4    (C_DIM / 4)
#define TB    32          // t per block
#define PADLO 12
#define BAND  56          // TB + PADLO + 12 rows

__global__ __launch_bounds__(256)
void shifting_band_kernel(const float* __restrict__ inp,
                          const float* __restrict__ sw,
                          float* __restrict__ out) {
    __shared__ float4 sm[BAND * C4];          // 56 rows * 512 B = 28672 B

    const int tid    = threadIdx.x;
    const int b      = blockIdx.y;
    const int t0_blk = blockIdx.x * TB;
    const int s_base = t0_blk - PADLO;

    const float4* __restrict__ src =
        (const float4*)(inp + (size_t)b * S_DIM * C_DIM);

    // ---- Stage band: 1792 float4 / 256 threads = 7 each, fully coalesced ----
#pragma unroll
    for (int i = 0; i < (BAND * C4) / 256; ++i) {
        const int k   = tid + i * 256;
        const int s   = s_base + (k >> 5);    // k/32 = band row
        sm[k] = (s >= 0) ? src[s * C4 + (k & 31)]
                         : make_float4(0.f, 0.f, 0.f, 0.f);
    }
    __syncthreads();

    // ---- Compute: warp owns 4 consecutive t, lane = 4 channels ----
    const int warp = tid >> 5;
    const int lane = tid & 31;
    const int t0_w = t0_blk + (warp << 2);

#pragma unroll
    for (int j = 0; j < 4; ++j) {
        const int   t = t0_w + j;
        const float w = sw[b * T_DIM + t];
        const int   r = __float2int_rn((float)t - w);

        float4 acc = make_float4(0.f, 0.f, 0.f, 0.f);
#pragma unroll
        for (int i = -1; i <= 1; ++i) {
            const int   s   = r + i;
            const float d   = w + (float)(s - t);
            const float wgt = __expf(-4.0f * d * d);
            const int   rel = s - s_base;

            float4 v;
            if ((unsigned)rel < BAND) {
                v = sm[rel * C4 + lane];              // hot path (always)
            } else if ((unsigned)s < S_DIM) {
                v = src[s * C4 + lane];               // out-of-band fallback
            } else {
                v = make_float4(0.f, 0.f, 0.f, 0.f);  // outside tensor
            }
            acc.x = fmaf(wgt, v.x, acc.x);
            acc.y = fmaf(wgt, v.y, acc.y);
            acc.z = fmaf(wgt, v.z, acc.z);
            acc.w = fmaf(wgt, v.w, acc.w);
        }

        float4* __restrict__ o =
            (float4*)(out + ((size_t)b * T_DIM + t) * C_DIM);
        o[lane] = acc;
    }
}

extern "C" void kernel_launch(void* const* d_in, const int* in_sizes, int n_in,
                              void* d_out, int out_size) {
    const float* inp = (const float*)d_in[0];   // (B, S, C) fp32
    const float* sw  = (const float*)d_in[1];   // (B, T)   fp32
    float* out       = (float*)d_out;           // (B, T, C) fp32

    dim3 grid(T_DIM / TB, 16, 1);   // (64, 16) = 1024 blocks
    dim3 block(256, 1, 1);
    shifting_band_kernel<<<grid, block>>>(inp, sw, out);
}

// round 6
// speedup vs baseline: 1.2007x; 1.2007x over previous
#include <cuda_runtime.h>

// out[b,t,c] = sum_s exp(-4*(sw[b,t] + s - t)^2) * input[b,s,c]
// WIDTH=0.25 -> weight = exp(-4 d^2). 3-tap window {r-1, r, r+1} around
// r = round(t - sw): dropped taps have |d| >= 1.5 -> wgt <= 1.23e-4 vs kept
// sum >= 0.74 -> worst-case rel err ~3e-4 (threshold 1e-3; measured 4.5e-5).
//
// B=16, S=4096, T=2048, C=128.
// Spread-reduction round: same per-warp work as round 4 (4 t per warp, two
// halves of 6 in-flight LDG.128, 32 regs) but 512-thread CTAs -> grid 512,
// oe ~3.5 CTAs/SM instead of 7. Per the B300 multi-CTA spread model
// (spr = 1.10 + 25*(oe*MLP_p1 - 16)/T_CTA) this cuts the cross-CTA L1tex
// queue spread from ~1.75x to ~1.25x of median CTA time.
// sw for the 4 t's is one float4 broadcast load. Bounds handled branch-free:
// load address clamped to s>=0, weight zeroed when s<0 (upper bound is
// structurally dead: s <= t + |sw| + 2 <= ~2054 < 4096).

#define S_DIM 4096
#define T_DIM 2048
#define C_DIM 128
#define C4    (C_DIM / 4)

__global__ __launch_bounds__(512)
void shifting_window_kernel(const float* __restrict__ inp,
                            const float* __restrict__ sw,
                            float* __restrict__ out) {
    const int b    = blockIdx.y;
    const int warp = threadIdx.x >> 5;                 // 0..15
    const int lane = threadIdx.x & 31;
    const int t0   = (blockIdx.x << 6) + (warp << 2);  // 4 t per warp

    const float4* __restrict__ row =
        (const float4*)(inp + (size_t)b * S_DIM * C_DIM);

    // One broadcast float4 covers sw[t0..t0+3] (t0 % 4 == 0, 16B-aligned).
    const float4 swv = *(const float4*)(sw + b * T_DIM + t0);
    const float w[4] = {swv.x, swv.y, swv.z, swv.w};

    int r[4];
#pragma unroll
    for (int j = 0; j < 4; ++j)
        r[j] = __float2int_rn((float)(t0 + j) - w[j]);  // window center

    // Two halves of 2 t each: peak 6 float4 loads in flight (24 regs).
#pragma unroll
    for (int half = 0; half < 2; ++half) {
        const int j0 = half << 1;
        float4 acc[2] = {make_float4(0.f, 0.f, 0.f, 0.f),
                         make_float4(0.f, 0.f, 0.f, 0.f)};
#pragma unroll
        for (int i = -1; i <= 1; ++i) {
#pragma unroll
            for (int jj = 0; jj < 2; ++jj) {
                const int   j    = j0 + jj;
                const int   s    = r[j] + i;
                const float d    = w[j] + (float)(s - (t0 + j));
                float       wgt  = __expf(-4.0f * d * d);
                if (s < 0) wgt = 0.f;                  // branch-free zero
                const int   s_ld = (s < 0) ? 0 : s;    // clamped safe address
                const float4 v   = row[s_ld * C4 + lane];
                acc[jj].x = fmaf(wgt, v.x, acc[jj].x);
                acc[jj].y = fmaf(wgt, v.y, acc[jj].y);
                acc[jj].z = fmaf(wgt, v.z, acc[jj].z);
                acc[jj].w = fmaf(wgt, v.w, acc[jj].w);
            }
        }
#pragma unroll
        for (int jj = 0; jj < 2; ++jj) {
            float4* __restrict__ o =
                (float4*)(out + ((size_t)b * T_DIM + (t0 + j0 + jj)) * C_DIM);
            o[lane] = acc[jj];
        }
    }
}

extern "C" void kernel_launch(void* const* d_in, const int* in_sizes, int n_in,
                              void* d_out, int out_size) {
    const float* inp = (const float*)d_in[0];   // (B, S, C) fp32
    const float* sw  = (const float*)d_in[1];   // (B, T)   fp32
    float* out       = (float*)d_out;           // (B, T, C) fp32

    dim3 grid(T_DIM / 64, 16, 1);   // 64 t per block -> (32, 16) = 512 blocks
    dim3 block(512, 1, 1);
    shifting_window_kernel<<<grid, block>>>(inp, sw, out);
}